// round 15
// baseline (speedup 1.0000x reference)
#include <cuda_runtime.h>
#include <cuda_fp16.h>
#include <cstdint>

// ============================================================================
// GraphConstructionActorHead — all N*N pair scores via factored 3-layer MLP.
//   pre: A[i]=emb_i@W1[:64]+b1, B[j]=emb_j@W1[64:] in transposed column-tile
//     layout; per-node (sum,sumsq); W2^T fp16 swizzled; LN1/LN2 g,be + W3 as
//     packed half2 -> __constant__; b2 as packed float2 -> __constant__.
//   main: tile = 128 pairs (one i, 128 j). Warp owns 32 rows end-to-end.
//     layer1: fp32 dot for LN stats, x as 32 half2 regs, LN1+ReLU in HFMA2 ->
//     smem -> ldmatrix -> single-pass fp16 mma.sync (b2 in accumulator init)
//     -> LN2 stats fp32 (shfl) -> y via half2 HFMA2/HMAX2 -> W3 dot via
//     mma.sync (A-frag == D-frag layout identity; b3 in acc init) -> store.
//   5 CTAs/SM (regs<=102; W3 frags via const port, not registers), single
//   wave, chunked schedule.
// ============================================================================

#define NN 1024
#define NUM_TILES 8192
#define GRID_MAIN 760              // 5 CTAs/SM * 152 SMs, single wave
#define SMEM_BYTES 25600

// ---------------- device scratch --------------------------------------------
__device__ float g_A[NN * 64];
__device__ float g_Bt[NN * 64];             // [jb][16 quads][128 rows][4]
__device__ float2 g_stA[NN];
__device__ float2 g_stB[NN];
__device__ __half g_w2hi[64 * 64];          // [n][k] rows of 128B, XOR-swizzled
__device__ uint32_t g_h2d[160];             // staging: g1h be1h w3h g2h be2h
__device__ float2 g_b2d[32];                // staging: b2 pairs

__constant__ uint32_t c_h2[160];            // [0:32) g1h [32:64) be1h
                                            // [64:96) w3h [96:128) g2h
                                            // [128:160) be2h
__constant__ float2 c_b2[32];               // (b2[2k], b2[2k+1])

// ---------------- PTX helpers (family-common only) --------------------------
__device__ __forceinline__ uint32_t smem_to_u32(const void* p) {
    uint32_t a;
    asm("{ .reg .u64 t; cvta.to.shared.u64 t, %1; cvt.u32.u64 %0, t; }"
        : "=r"(a) : "l"(p));
    return a;
}
__device__ __forceinline__ void ldm_x4(uint32_t* r, uint32_t addr) {
    asm volatile("ldmatrix.sync.aligned.m8n8.x4.shared.b16 {%0,%1,%2,%3}, [%4];"
                 : "=r"(r[0]), "=r"(r[1]), "=r"(r[2]), "=r"(r[3]) : "r"(addr));
}
__device__ __forceinline__ void mma_f16(float* c, const uint32_t* a,
                                        uint32_t b0, uint32_t b1) {
    asm volatile(
        "mma.sync.aligned.m16n8k16.row.col.f32.f16.f16.f32 "
        "{%0,%1,%2,%3}, {%4,%5,%6,%7}, {%8,%9}, {%0,%1,%2,%3};"
        : "+f"(c[0]), "+f"(c[1]), "+f"(c[2]), "+f"(c[3])
        : "r"(a[0]), "r"(a[1]), "r"(a[2]), "r"(a[3]), "r"(b0), "r"(b1));
}
__device__ __forceinline__ int swz(int row, int chunk) {
    return row * 128 + ((chunk ^ (row & 7)) << 4);
}
__device__ __forceinline__ uint32_t h2bits(__half2 h) { return *(uint32_t*)&h; }
__device__ __forceinline__ __half2 bits2h(uint32_t u) { return *(__half2*)&u; }

// ---------------- merged precompute (1 launch, 130 blocks x 512) ------------
__global__ void precompute_all(const float* __restrict__ emb,
                               const float* __restrict__ W1,
                               const float* __restrict__ b1,
                               const float* __restrict__ W2,
                               const float* __restrict__ g1, const float* __restrict__ be1,
                               const float* __restrict__ g2, const float* __restrict__ be2,
                               const float* __restrict__ W3, const float* __restrict__ b2) {
    int bid = blockIdx.x;
    int tid = threadIdx.x;
    if (bid < 128) {
        __shared__ float e[8][64];
        __shared__ float part[8][2][4];
        int g = tid >> 6, h = tid & 63;
        int n = bid * 8 + g;
        e[g][h] = emb[n * 64 + h];
        __syncthreads();
        float a0 = b1[h], a1 = 0.f, c0 = 0.f, c1 = 0.f;
#pragma unroll
        for (int d = 0; d < 64; d += 2) {
            float e0 = e[g][d], e1 = e[g][d + 1];
            a0 = fmaf(e0, __ldg(W1 + d * 64 + h), a0);
            a1 = fmaf(e1, __ldg(W1 + (d + 1) * 64 + h), a1);
            c0 = fmaf(e0, __ldg(W1 + (64 + d) * 64 + h), c0);
            c1 = fmaf(e1, __ldg(W1 + (65 + d) * 64 + h), c1);
        }
        float a = a0 + a1, b = c0 + c1;
        g_A[n * 64 + h] = a;
        g_Bt[(((n >> 7) * 16 + (h >> 2)) * 128 + (n & 127)) * 4 + (h & 3)] = b;
        float sa = a, qa = a * a, sb = b, qb = b * b;
#pragma unroll
        for (int o = 16; o > 0; o >>= 1) {
            sa += __shfl_xor_sync(0xffffffffu, sa, o);
            qa += __shfl_xor_sync(0xffffffffu, qa, o);
            sb += __shfl_xor_sync(0xffffffffu, sb, o);
            qb += __shfl_xor_sync(0xffffffffu, qb, o);
        }
        int w = (tid >> 5) & 1;
        if ((tid & 31) == 0) {
            part[g][w][0] = sa; part[g][w][1] = qa;
            part[g][w][2] = sb; part[g][w][3] = qb;
        }
        __syncthreads();
        if (tid < 8) {
            int nn = bid * 8 + tid;
            g_stA[nn] = make_float2(part[tid][0][0] + part[tid][1][0],
                                    part[tid][0][1] + part[tid][1][1]);
            g_stB[nn] = make_float2(part[tid][0][2] + part[tid][1][2],
                                    part[tid][0][3] + part[tid][1][3]);
        }
    } else if (bid == 128) {
#pragma unroll
        for (int u = 0; u < 8; u++) {
            int idx = tid + 512 * u;               // 0..4095
            int k = idx >> 6, n = idx & 63;
            float v = W2[k * 64 + n];              // B[n][k] = W2[k][n]
            int byte = swz(n, k >> 3) + (k & 7) * 2;
            g_w2hi[byte >> 1] = __float2half_rn(v);
        }
    } else {
        if (tid < 32) {
            g_h2d[tid]       = h2bits(__floats2half2_rn(g1[2 * tid], g1[2 * tid + 1]));
            g_h2d[32 + tid]  = h2bits(__floats2half2_rn(be1[2 * tid], be1[2 * tid + 1]));
            g_h2d[64 + tid]  = h2bits(__floats2half2_rn(W3[2 * tid], W3[2 * tid + 1]));
            g_h2d[96 + tid]  = h2bits(__floats2half2_rn(g2[2 * tid], g2[2 * tid + 1]));
            g_h2d[128 + tid] = h2bits(__floats2half2_rn(be2[2 * tid], be2[2 * tid + 1]));
            g_b2d[tid]       = make_float2(b2[2 * tid], b2[2 * tid + 1]);
        }
    }
}

// ---------------- main fused pair-MLP kernel --------------------------------
__global__ void __launch_bounds__(128, 5) pair_mlp_kernel(
    const float* __restrict__ mask, const float* __restrict__ b3p,
    float* __restrict__ out) {
    extern __shared__ char smem_raw[];
    uint32_t smem_u = smem_to_u32(smem_raw);
    uint32_t base = (smem_u + 1023) & ~1023u;
    char* basep = smem_raw + (base - smem_u);

    const uint32_t OFF_AHI = 0;        // h1 fp16 [128 rows x 128B] 16 KB
    const uint32_t OFF_BHI = 16384;    // W2^T fp16 [64 x 128B]      8 KB

    int tid = threadIdx.x;
    int l = tid & 31;
    int wb = (tid >> 5) << 5;          // warp's 32-row slice base

    // copy pre-swizzled W2 into smem (startup only)
    {
        uint4* ph = (uint4*)(basep + OFF_BHI);
        const uint4* shi = (const uint4*)g_w2hi;
#pragma unroll
        for (int t = 0; t < 4; t++) ph[tid + 128 * t] = __ldg(shi + tid + 128 * t);
    }
    __syncthreads();

    float b3 = __ldg(b3p);
    int arow_lo = ((l >> 3) & 1) * 8 + (l & 7);
    int asel = l >> 4;
    int brow = (l & 7);
    int bnb_hi = (l >> 4) & 1;
    int bchunk = (l >> 3) & 1;
    int c4 = l & 3;

    // chunked schedule: consecutive tiles share jbase -> Bt block L1-resident
    int t0 = (int)(((long long)blockIdx.x * NUM_TILES) / GRID_MAIN);
    int t1 = (int)(((long long)(blockIdx.x + 1) * NUM_TILES) / GRID_MAIN);

    for (int T = t0; T < t1; T++) {
        int i = T & 1023;
        int jbase = (T >> 10) << 7;

        const float4* Ar = (const float4*)(g_A + i * 64);
        const float4* Br = (const float4*)g_Bt + (size_t)(T >> 10) * 2048 + tid;

        // ---- layer 1: fp32 dot for stats; x packed to half2 regs -----------
        float d0 = 0, d1 = 0, d2 = 0, d3 = 0;
        uint32_t xh[32];
#pragma unroll
        for (int t = 0; t < 16; t++) {
            float4 a = __ldg(Ar + t);
            float4 b = __ldg(Br + t * 128);        // coalesced: lane = row
            d0 = fmaf(a.x, b.x, d0); d1 = fmaf(a.y, b.y, d1);
            d2 = fmaf(a.z, b.z, d2); d3 = fmaf(a.w, b.w, d3);
            xh[2 * t]     = h2bits(__floats2half2_rn(a.x + b.x, a.y + b.y));
            xh[2 * t + 1] = h2bits(__floats2half2_rn(a.z + b.z, a.w + b.w));
        }
        float2 stA = __ldg(g_stA + i);
        float2 stB = __ldg(g_stB + jbase + tid);
        float dot = (d0 + d1) + (d2 + d3);
        float m  = (stA.x + stB.x) * (1.f / 64.f);
        float v  = (stA.y + stB.y + 2.f * dot) * (1.f / 64.f) - m * m;
        float rs = rsqrtf(v + 1e-5f);
        float nm = -m * rs;

        // LN1 + ReLU in half2, STS to warp-private rows
        __half2 rsh = __float2half2_rn(rs);
        __half2 nmh = __float2half2_rn(nm);
        __half2 z2 = __float2half2_rn(0.f);
#pragma unroll
        for (int c = 0; c < 8; c++) {
            uint32_t hiw[4];
#pragma unroll
            for (int u = 0; u < 4; u++) {
                int k2 = 4 * c + u;
                __half2 u0 = __hfma2(bits2h(xh[k2]), rsh, nmh);
                __half2 h = __hmax2(__hfma2(u0, bits2h(c_h2[k2]),
                                            bits2h(c_h2[32 + k2])), z2);
                hiw[u] = h2bits(h);
            }
            int off = swz(tid, c);
            *(uint4*)(basep + OFF_AHI + off) = make_uint4(hiw[0], hiw[1], hiw[2], hiw[3]);
        }
        __syncwarp();   // warp-private rows: only intra-warp visibility needed

        // ---- layer 2 GEMM: single-pass fp16, b2 in accumulator init --------
        float acc[2][8][4];
#pragma unroll
        for (int nb = 0; nb < 8; nb++) {
            float2 bb = c_b2[nb * 4 + c4];         // (b2[col], b2[col+1])
            acc[0][nb][0] = bb.x; acc[0][nb][1] = bb.y;
            acc[0][nb][2] = bb.x; acc[0][nb][3] = bb.y;
            acc[1][nb][0] = bb.x; acc[1][nb][1] = bb.y;
            acc[1][nb][2] = bb.x; acc[1][nb][3] = bb.y;
        }
#pragma unroll
        for (int kc = 0; kc < 4; kc++) {
            uint32_t ahi0[4], ahi1[4];
            ldm_x4(ahi0, base + OFF_AHI + swz(wb + arow_lo, kc * 2 + asel));
            ldm_x4(ahi1, base + OFF_AHI + swz(wb + 16 + arow_lo, kc * 2 + asel));
#pragma unroll
            for (int p = 0; p < 4; p++) {
                uint32_t r[4];
                ldm_x4(r, base + OFF_BHI +
                           swz((2 * p + bnb_hi) * 8 + brow, kc * 2 + bchunk));
                mma_f16(acc[0][2 * p],     ahi0, r[0], r[1]);
                mma_f16(acc[1][2 * p],     ahi1, r[0], r[1]);
                mma_f16(acc[0][2 * p + 1], ahi0, r[2], r[3]);
                mma_f16(acc[1][2 * p + 1], ahi1, r[2], r[3]);
            }
        }

        // ---- LN2 stats fp32 (b2 already in acc), shfl reduce ---------------
        float rs0[2], nm0[2], rs1[2], nm1[2];
#pragma unroll
        for (int mf = 0; mf < 2; mf++) {
            float su0 = 0, qu0 = 0, su1 = 0, qu1 = 0;
#pragma unroll
            for (int nb = 0; nb < 8; nb++) {
                float a0 = acc[mf][nb][0], a1 = acc[mf][nb][1];
                float a2 = acc[mf][nb][2], a3 = acc[mf][nb][3];
                su0 += a0 + a1; qu0 = fmaf(a0, a0, fmaf(a1, a1, qu0));
                su1 += a2 + a3; qu1 = fmaf(a2, a2, fmaf(a3, a3, qu1));
            }
            su0 += __shfl_xor_sync(0xffffffffu, su0, 1);
            su0 += __shfl_xor_sync(0xffffffffu, su0, 2);
            qu0 += __shfl_xor_sync(0xffffffffu, qu0, 1);
            qu0 += __shfl_xor_sync(0xffffffffu, qu0, 2);
            su1 += __shfl_xor_sync(0xffffffffu, su1, 1);
            su1 += __shfl_xor_sync(0xffffffffu, su1, 2);
            qu1 += __shfl_xor_sync(0xffffffffu, qu1, 1);
            qu1 += __shfl_xor_sync(0xffffffffu, qu1, 2);
            float m0 = su0 * (1.f / 64.f);
            float v0 = qu0 * (1.f / 64.f) - m0 * m0;
            rs0[mf] = rsqrtf(v0 + 1e-5f); nm0[mf] = -m0 * rs0[mf];
            float m1 = su1 * (1.f / 64.f);
            float v1 = qu1 * (1.f / 64.f) - m1 * m1;
            rs1[mf] = rsqrtf(v1 + 1e-5f); nm1[mf] = -m1 * rs1[mf];
        }

        // ---- y = relu(LN2) in half2 -> W3 dot via mma (b3 in acc init) -----
        // W3 B-fragments come straight off the constant port (saves 8 regs)
        float w00, w01, w10, w11;
#pragma unroll
        for (int mf = 0; mf < 2; mf++) {
            float c2[4] = {b3, b3, b3, b3};
            __half2 rg = __float2half2_rn(rs0[mf]), ng = __float2half2_rn(nm0[mf]);
            __half2 r8 = __float2half2_rn(rs1[mf]), n8 = __float2half2_rn(nm1[mf]);
#pragma unroll
            for (int p = 0; p < 4; p++) {
                int nA = 2 * p, nB = 2 * p + 1;
                int kA = nA * 4 + c4, kB = nB * 4 + c4;   // half2 col-pair idx
                __half2 gA = bits2h(c_h2[96 + kA]), bA = bits2h(c_h2[128 + kA]);
                __half2 gB = bits2h(c_h2[96 + kB]), bB = bits2h(c_h2[128 + kB]);
                uint32_t af[4];
                __half2 zz, uu;
                zz = __floats2half2_rn(acc[mf][nA][0], acc[mf][nA][1]);
                uu = __hfma2(zz, rg, ng);
                af[0] = h2bits(__hmax2(__hfma2(uu, gA, bA), z2));
                zz = __floats2half2_rn(acc[mf][nA][2], acc[mf][nA][3]);
                uu = __hfma2(zz, r8, n8);
                af[1] = h2bits(__hmax2(__hfma2(uu, gA, bA), z2));
                zz = __floats2half2_rn(acc[mf][nB][0], acc[mf][nB][1]);
                uu = __hfma2(zz, rg, ng);
                af[2] = h2bits(__hmax2(__hfma2(uu, gB, bB), z2));
                zz = __floats2half2_rn(acc[mf][nB][2], acc[mf][nB][3]);
                uu = __hfma2(zz, r8, n8);
                af[3] = h2bits(__hmax2(__hfma2(uu, gB, bB), z2));
                mma_f16(c2, af, c_h2[64 + 8 * p + c4], c_h2[64 + 8 * p + c4 + 4]);
            }
            if (mf == 0) { w00 = c2[0]; w01 = c2[2]; }
            else         { w10 = c2[0]; w11 = c2[2]; }
        }

        // gather so lane l holds row wb+l -> coalesced mask load + store
        int src = (l & 7) * 4;
        float a0 = __shfl_sync(0xffffffffu, w00, src);
        float a1 = __shfl_sync(0xffffffffu, w01, src);
        float a2 = __shfl_sync(0xffffffffu, w10, src);
        float a3 = __shfl_sync(0xffffffffu, w11, src);
        float dv = (l < 8) ? a0 : (l < 16) ? a1 : (l < 24) ? a2 : a3;
        int jj = jbase + wb + l;
        int p = (i << 10) + jj;
        float sc = dv * __ldg(mask + p);
        out[p] = (jj == i) ? 0.f : sc;

        __syncwarp();   // lanes rejoin before next tile's STS to the warp slice
    }
}

// ---------------- launch ----------------------------------------------------
extern "C" void kernel_launch(void* const* d_in, const int* in_sizes, int n_in,
                              void* d_out, int out_size) {
    const float* emb  = (const float*)d_in[0];
    const float* mask = (const float*)d_in[1];
    const float* W1   = (const float*)d_in[2];
    const float* b1   = (const float*)d_in[3];
    const float* g1   = (const float*)d_in[4];
    const float* be1  = (const float*)d_in[5];
    const float* W2   = (const float*)d_in[6];
    const float* b2   = (const float*)d_in[7];
    const float* g2   = (const float*)d_in[8];
    const float* be2  = (const float*)d_in[9];
    const float* W3   = (const float*)d_in[10];
    const float* b3   = (const float*)d_in[11];
    float* out = (float*)d_out;

    cudaFuncSetAttribute(pair_mlp_kernel,
                         cudaFuncAttributeMaxDynamicSharedMemorySize, SMEM_BYTES);

    precompute_all<<<130, 512>>>(emb, W1, b1, W2, g1, be1, g2, be2, W3, b2);

    // stage packed consts into __constant__ (async D2D copies, capturable)
    void* ph2 = nullptr; void* pb2 = nullptr;
    cudaGetSymbolAddress(&ph2, g_h2d);
    cudaGetSymbolAddress(&pb2, g_b2d);
    cudaMemcpyToSymbolAsync(c_h2, ph2, 160 * sizeof(uint32_t), 0,
                            cudaMemcpyDeviceToDevice, 0);
    cudaMemcpyToSymbolAsync(c_b2, pb2, 32 * sizeof(float2), 0,
                            cudaMemcpyDeviceToDevice, 0);

    pair_mlp_kernel<<<GRID_MAIN, 128, SMEM_BYTES>>>(mask, b3, out);
}

// round 16
// speedup vs baseline: 1.0240x; 1.0240x over previous
#include <cuda_runtime.h>
#include <cuda_fp16.h>
#include <cstdint>

// ============================================================================
// GraphConstructionActorHead — all N*N pair scores via factored 3-layer MLP.
//   pre: A[i]=emb_i@W1[:64]+b1, B[j]=emb_j@W1[64:] in transposed column-tile
//     layout; per-node (sum,sumsq); W2^T fp16 swizzled; LN1/LN2 g,be + W3 +
//     b2 packed into ONE __constant__ block.
//   main: tile = 128 pairs (one i, 128 j). Warp owns 32 rows end-to-end.
//     layer1: fp32 dot for LN stats, x as 32 half2 regs, LN1+ReLU in HFMA2 ->
//     smem -> ldmatrix -> single-pass fp16 mma.sync (b2 in accumulator init)
//     -> LN2 stats fp32 (shfl) -> y via half2 HFMA2/HMAX2 -> W3 dot via
//     mma.sync -> store.
//   5 CTAs/SM. Schedule: jblock = bid%8 so ALL co-resident CTAs (bids differ
//   by multiples of 152 ≡ 0 mod 8) share one 32KB Bt block in L1 — fixes the
//   R15 L1-capacity thrash that inverted the occupancy win.
// ============================================================================

#define NN 1024
#define GRID_MAIN 760              // 8 jblocks x 95 i-chunks; 5 CTAs/SM
#define SMEM_BYTES 25600

// ---------------- device scratch --------------------------------------------
__device__ float g_A[NN * 64];
__device__ float g_Bt[NN * 64];             // [jb][16 quads][128 rows][4]
__device__ float2 g_stA[NN];
__device__ float2 g_stB[NN];
__device__ __half g_w2hi[64 * 64];          // [n][k] rows of 128B, XOR-swizzled
__device__ __align__(16) uint32_t g_alld[224]; // staging for c_all

// c_all layout (u32 idx): [0:32) g1h2 [32:64) be1h2 [64:96) w3h2
//                         [96:128) g2h2 [128:160) be2h2 [160:224) b2 float2
__constant__ __align__(16) uint32_t c_all[224];

// ---------------- PTX helpers (family-common only) --------------------------
__device__ __forceinline__ uint32_t smem_to_u32(const void* p) {
    uint32_t a;
    asm("{ .reg .u64 t; cvta.to.shared.u64 t, %1; cvt.u32.u64 %0, t; }"
        : "=r"(a) : "l"(p));
    return a;
}
__device__ __forceinline__ void ldm_x4(uint32_t* r, uint32_t addr) {
    asm volatile("ldmatrix.sync.aligned.m8n8.x4.shared.b16 {%0,%1,%2,%3}, [%4];"
                 : "=r"(r[0]), "=r"(r[1]), "=r"(r[2]), "=r"(r[3]) : "r"(addr));
}
__device__ __forceinline__ void mma_f16(float* c, const uint32_t* a,
                                        uint32_t b0, uint32_t b1) {
    asm volatile(
        "mma.sync.aligned.m16n8k16.row.col.f32.f16.f16.f32 "
        "{%0,%1,%2,%3}, {%4,%5,%6,%7}, {%8,%9}, {%0,%1,%2,%3};"
        : "+f"(c[0]), "+f"(c[1]), "+f"(c[2]), "+f"(c[3])
        : "r"(a[0]), "r"(a[1]), "r"(a[2]), "r"(a[3]), "r"(b0), "r"(b1));
}
__device__ __forceinline__ int swz(int row, int chunk) {
    return row * 128 + ((chunk ^ (row & 7)) << 4);
}
__device__ __forceinline__ uint32_t h2bits(__half2 h) { return *(uint32_t*)&h; }
__device__ __forceinline__ __half2 bits2h(uint32_t u) { return *(__half2*)&u; }

// ---------------- merged precompute (1 launch, 130 blocks x 512) ------------
__global__ void precompute_all(const float* __restrict__ emb,
                               const float* __restrict__ W1,
                               const float* __restrict__ b1,
                               const float* __restrict__ W2,
                               const float* __restrict__ g1, const float* __restrict__ be1,
                               const float* __restrict__ g2, const float* __restrict__ be2,
                               const float* __restrict__ W3, const float* __restrict__ b2) {
    int bid = blockIdx.x;
    int tid = threadIdx.x;
    if (bid < 128) {
        __shared__ float e[8][64];
        __shared__ float part[8][2][4];
        int g = tid >> 6, h = tid & 63;
        int n = bid * 8 + g;
        e[g][h] = emb[n * 64 + h];
        __syncthreads();
        float a0 = b1[h], a1 = 0.f, c0 = 0.f, c1 = 0.f;
#pragma unroll
        for (int d = 0; d < 64; d += 2) {
            float e0 = e[g][d], e1 = e[g][d + 1];
            a0 = fmaf(e0, __ldg(W1 + d * 64 + h), a0);
            a1 = fmaf(e1, __ldg(W1 + (d + 1) * 64 + h), a1);
            c0 = fmaf(e0, __ldg(W1 + (64 + d) * 64 + h), c0);
            c1 = fmaf(e1, __ldg(W1 + (65 + d) * 64 + h), c1);
        }
        float a = a0 + a1, b = c0 + c1;
        g_A[n * 64 + h] = a;
        g_Bt[(((n >> 7) * 16 + (h >> 2)) * 128 + (n & 127)) * 4 + (h & 3)] = b;
        float sa = a, qa = a * a, sb = b, qb = b * b;
#pragma unroll
        for (int o = 16; o > 0; o >>= 1) {
            sa += __shfl_xor_sync(0xffffffffu, sa, o);
            qa += __shfl_xor_sync(0xffffffffu, qa, o);
            sb += __shfl_xor_sync(0xffffffffu, sb, o);
            qb += __shfl_xor_sync(0xffffffffu, qb, o);
        }
        int w = (tid >> 5) & 1;
        if ((tid & 31) == 0) {
            part[g][w][0] = sa; part[g][w][1] = qa;
            part[g][w][2] = sb; part[g][w][3] = qb;
        }
        __syncthreads();
        if (tid < 8) {
            int nn = bid * 8 + tid;
            g_stA[nn] = make_float2(part[tid][0][0] + part[tid][1][0],
                                    part[tid][0][1] + part[tid][1][1]);
            g_stB[nn] = make_float2(part[tid][0][2] + part[tid][1][2],
                                    part[tid][0][3] + part[tid][1][3]);
        }
    } else if (bid == 128) {
#pragma unroll
        for (int u = 0; u < 8; u++) {
            int idx = tid + 512 * u;               // 0..4095
            int k = idx >> 6, n = idx & 63;
            float v = W2[k * 64 + n];              // B[n][k] = W2[k][n]
            int byte = swz(n, k >> 3) + (k & 7) * 2;
            g_w2hi[byte >> 1] = __float2half_rn(v);
        }
    } else {
        if (tid < 32) {
            g_alld[tid]       = h2bits(__floats2half2_rn(g1[2 * tid], g1[2 * tid + 1]));
            g_alld[32 + tid]  = h2bits(__floats2half2_rn(be1[2 * tid], be1[2 * tid + 1]));
            g_alld[64 + tid]  = h2bits(__floats2half2_rn(W3[2 * tid], W3[2 * tid + 1]));
            g_alld[96 + tid]  = h2bits(__floats2half2_rn(g2[2 * tid], g2[2 * tid + 1]));
            g_alld[128 + tid] = h2bits(__floats2half2_rn(be2[2 * tid], be2[2 * tid + 1]));
            ((float2*)&g_alld[160])[tid] = make_float2(b2[2 * tid], b2[2 * tid + 1]);
        }
    }
}

// ---------------- main fused pair-MLP kernel --------------------------------
__global__ void __launch_bounds__(128, 5) pair_mlp_kernel(
    const float* __restrict__ mask, const float* __restrict__ b3p,
    float* __restrict__ out) {
    extern __shared__ char smem_raw[];
    uint32_t smem_u = smem_to_u32(smem_raw);
    uint32_t base = (smem_u + 1023) & ~1023u;
    char* basep = smem_raw + (base - smem_u);

    const uint32_t OFF_AHI = 0;        // h1 fp16 [128 rows x 128B] 16 KB
    const uint32_t OFF_BHI = 16384;    // W2^T fp16 [64 x 128B]      8 KB

    int tid = threadIdx.x;
    int l = tid & 31;
    int wb = (tid >> 5) << 5;          // warp's 32-row slice base

    // copy pre-swizzled W2 into smem (startup only)
    {
        uint4* ph = (uint4*)(basep + OFF_BHI);
        const uint4* shi = (const uint4*)g_w2hi;
#pragma unroll
        for (int t = 0; t < 4; t++) ph[tid + 128 * t] = __ldg(shi + tid + 128 * t);
    }
    __syncthreads();

    float b3 = __ldg(b3p);
    int arow_lo = ((l >> 3) & 1) * 8 + (l & 7);
    int asel = l >> 4;
    int brow = (l & 7);
    int bnb_hi = (l >> 4) & 1;
    int bchunk = (l >> 3) & 1;
    int c4 = l & 3;
    const float2* cb2 = (const float2*)&c_all[160];

    // schedule: co-resident CTAs (bid ± k*152, 152 % 8 == 0) share jblock
    int jb = blockIdx.x & 7;
    int ic = blockIdx.x >> 3;          // 0..94
    int i0 = (ic * NN) / 95;
    int i1 = ((ic + 1) * NN) / 95;
    int jbase = jb << 7;

    // per-tile-invariant hoists
    const float4* Brp = (const float4*)g_Bt + (size_t)jb * 2048 + tid;
    float2 stB = __ldg(g_stB + jbase + tid);
    int jj = jbase + wb + l;
    const float* maskp = mask + jj;
    float* outp = out + jj;
    __half2 z2 = __float2half2_rn(0.f);

    for (int i = i0; i < i1; i++) {
        const float4* Ar = (const float4*)(g_A + i * 64);

        // ---- layer 1: fp32 dot for stats; x packed to half2 regs -----------
        float d0 = 0, d1 = 0, d2 = 0, d3 = 0;
        uint32_t xh[32];
#pragma unroll
        for (int t = 0; t < 16; t++) {
            float4 a = __ldg(Ar + t);
            float4 b = __ldg(Brp + t * 128);       // coalesced: lane = row
            d0 = fmaf(a.x, b.x, d0); d1 = fmaf(a.y, b.y, d1);
            d2 = fmaf(a.z, b.z, d2); d3 = fmaf(a.w, b.w, d3);
            xh[2 * t]     = h2bits(__floats2half2_rn(a.x + b.x, a.y + b.y));
            xh[2 * t + 1] = h2bits(__floats2half2_rn(a.z + b.z, a.w + b.w));
        }
        float2 stA = __ldg(g_stA + i);
        float dot = (d0 + d1) + (d2 + d3);
        float m  = (stA.x + stB.x) * (1.f / 64.f);
        float v  = (stA.y + stB.y + 2.f * dot) * (1.f / 64.f) - m * m;
        float rs = rsqrtf(v + 1e-5f);
        float nm = -m * rs;

        // LN1 + ReLU in half2, STS to warp-private rows
        __half2 rsh = __float2half2_rn(rs);
        __half2 nmh = __float2half2_rn(nm);
#pragma unroll
        for (int c = 0; c < 8; c++) {
            uint32_t hiw[4];
#pragma unroll
            for (int u = 0; u < 4; u++) {
                int k2 = 4 * c + u;
                __half2 u0 = __hfma2(bits2h(xh[k2]), rsh, nmh);
                __half2 h = __hmax2(__hfma2(u0, bits2h(c_all[k2]),
                                            bits2h(c_all[32 + k2])), z2);
                hiw[u] = h2bits(h);
            }
            int off = swz(tid, c);
            *(uint4*)(basep + OFF_AHI + off) = make_uint4(hiw[0], hiw[1], hiw[2], hiw[3]);
        }
        __syncwarp();   // warp-private rows: only intra-warp visibility needed

        // ---- layer 2 GEMM: single-pass fp16, b2 in accumulator init --------
        float acc[2][8][4];
#pragma unroll
        for (int nb = 0; nb < 8; nb++) {
            float2 bb = cb2[nb * 4 + c4];          // (b2[col], b2[col+1])
            acc[0][nb][0] = bb.x; acc[0][nb][1] = bb.y;
            acc[0][nb][2] = bb.x; acc[0][nb][3] = bb.y;
            acc[1][nb][0] = bb.x; acc[1][nb][1] = bb.y;
            acc[1][nb][2] = bb.x; acc[1][nb][3] = bb.y;
        }
#pragma unroll
        for (int kc = 0; kc < 4; kc++) {
            uint32_t ahi0[4], ahi1[4];
            ldm_x4(ahi0, base + OFF_AHI + swz(wb + arow_lo, kc * 2 + asel));
            ldm_x4(ahi1, base + OFF_AHI + swz(wb + 16 + arow_lo, kc * 2 + asel));
#pragma unroll
            for (int p = 0; p < 4; p++) {
                uint32_t r[4];
                ldm_x4(r, base + OFF_BHI +
                           swz((2 * p + bnb_hi) * 8 + brow, kc * 2 + bchunk));
                mma_f16(acc[0][2 * p],     ahi0, r[0], r[1]);
                mma_f16(acc[1][2 * p],     ahi1, r[0], r[1]);
                mma_f16(acc[0][2 * p + 1], ahi0, r[2], r[3]);
                mma_f16(acc[1][2 * p + 1], ahi1, r[2], r[3]);
            }
        }

        // ---- LN2 stats fp32 (b2 already in acc), shfl reduce ---------------
        float rs0[2], nm0[2], rs1[2], nm1[2];
#pragma unroll
        for (int mf = 0; mf < 2; mf++) {
            float su0 = 0, qu0 = 0, su1 = 0, qu1 = 0;
#pragma unroll
            for (int nb = 0; nb < 8; nb++) {
                float a0 = acc[mf][nb][0], a1 = acc[mf][nb][1];
                float a2 = acc[mf][nb][2], a3 = acc[mf][nb][3];
                su0 += a0 + a1; qu0 = fmaf(a0, a0, fmaf(a1, a1, qu0));
                su1 += a2 + a3; qu1 = fmaf(a2, a2, fmaf(a3, a3, qu1));
            }
            su0 += __shfl_xor_sync(0xffffffffu, su0, 1);
            su0 += __shfl_xor_sync(0xffffffffu, su0, 2);
            qu0 += __shfl_xor_sync(0xffffffffu, qu0, 1);
            qu0 += __shfl_xor_sync(0xffffffffu, qu0, 2);
            su1 += __shfl_xor_sync(0xffffffffu, su1, 1);
            su1 += __shfl_xor_sync(0xffffffffu, su1, 2);
            qu1 += __shfl_xor_sync(0xffffffffu, qu1, 1);
            qu1 += __shfl_xor_sync(0xffffffffu, qu1, 2);
            float m0 = su0 * (1.f / 64.f);
            float v0 = qu0 * (1.f / 64.f) - m0 * m0;
            rs0[mf] = rsqrtf(v0 + 1e-5f); nm0[mf] = -m0 * rs0[mf];
            float m1 = su1 * (1.f / 64.f);
            float v1 = qu1 * (1.f / 64.f) - m1 * m1;
            rs1[mf] = rsqrtf(v1 + 1e-5f); nm1[mf] = -m1 * rs1[mf];
        }

        // ---- y = relu(LN2) in half2 -> W3 dot via mma (b3 in acc init) -----
        float w00, w01, w10, w11;
#pragma unroll
        for (int mf = 0; mf < 2; mf++) {
            float c2[4] = {b3, b3, b3, b3};
            __half2 rg = __float2half2_rn(rs0[mf]), ng = __float2half2_rn(nm0[mf]);
            __half2 r8 = __float2half2_rn(rs1[mf]), n8 = __float2half2_rn(nm1[mf]);
#pragma unroll
            for (int p = 0; p < 4; p++) {
                int nA = 2 * p, nB = 2 * p + 1;
                int kA = nA * 4 + c4, kB = nB * 4 + c4;   // half2 col-pair idx
                __half2 gA = bits2h(c_all[96 + kA]), bA = bits2h(c_all[128 + kA]);
                __half2 gB = bits2h(c_all[96 + kB]), bB = bits2h(c_all[128 + kB]);
                uint32_t af[4];
                __half2 zz, uu;
                zz = __floats2half2_rn(acc[mf][nA][0], acc[mf][nA][1]);
                uu = __hfma2(zz, rg, ng);
                af[0] = h2bits(__hmax2(__hfma2(uu, gA, bA), z2));
                zz = __floats2half2_rn(acc[mf][nA][2], acc[mf][nA][3]);
                uu = __hfma2(zz, r8, n8);
                af[1] = h2bits(__hmax2(__hfma2(uu, gA, bA), z2));
                zz = __floats2half2_rn(acc[mf][nB][0], acc[mf][nB][1]);
                uu = __hfma2(zz, rg, ng);
                af[2] = h2bits(__hmax2(__hfma2(uu, gB, bB), z2));
                zz = __floats2half2_rn(acc[mf][nB][2], acc[mf][nB][3]);
                uu = __hfma2(zz, r8, n8);
                af[3] = h2bits(__hmax2(__hfma2(uu, gB, bB), z2));
                mma_f16(c2, af, c_all[64 + 8 * p + c4], c_all[64 + 8 * p + c4 + 4]);
            }
            if (mf == 0) { w00 = c2[0]; w01 = c2[2]; }
            else         { w10 = c2[0]; w11 = c2[2]; }
        }

        // gather so lane l holds row wb+l -> coalesced mask load + store
        int src = (l & 7) * 4;
        float a0 = __shfl_sync(0xffffffffu, w00, src);
        float a1 = __shfl_sync(0xffffffffu, w01, src);
        float a2 = __shfl_sync(0xffffffffu, w10, src);
        float a3 = __shfl_sync(0xffffffffu, w11, src);
        float dv = (l < 8) ? a0 : (l < 16) ? a1 : (l < 24) ? a2 : a3;
        float sc = dv * __ldg(maskp + (i << 10));
        outp[i << 10] = (jj == i) ? 0.f : sc;

        __syncwarp();   // lanes rejoin before next tile's STS to the warp slice
    }
}

// ---------------- launch ----------------------------------------------------
extern "C" void kernel_launch(void* const* d_in, const int* in_sizes, int n_in,
                              void* d_out, int out_size) {
    const float* emb  = (const float*)d_in[0];
    const float* mask = (const float*)d_in[1];
    const float* W1   = (const float*)d_in[2];
    const float* b1   = (const float*)d_in[3];
    const float* g1   = (const float*)d_in[4];
    const float* be1  = (const float*)d_in[5];
    const float* W2   = (const float*)d_in[6];
    const float* b2   = (const float*)d_in[7];
    const float* g2   = (const float*)d_in[8];
    const float* be2  = (const float*)d_in[9];
    const float* W3   = (const float*)d_in[10];
    const float* b3   = (const float*)d_in[11];
    float* out = (float*)d_out;

    cudaFuncSetAttribute(pair_mlp_kernel,
                         cudaFuncAttributeMaxDynamicSharedMemorySize, SMEM_BYTES);

    precompute_all<<<130, 512>>>(emb, W1, b1, W2, g1, be1, g2, be2, W3, b2);

    // stage packed consts into __constant__ (single async D2D copy)
    void* pall = nullptr;
    cudaGetSymbolAddress(&pall, g_alld);
    cudaMemcpyToSymbolAsync(c_all, pall, 224 * sizeof(uint32_t), 0,
                            cudaMemcpyDeviceToDevice, 0);

    pair_mlp_kernel<<<GRID_MAIN, 128, SMEM_BYTES>>>(mask, b3, out);
}

// round 17
// speedup vs baseline: 1.0639x; 1.0390x over previous
#include <cuda_runtime.h>
#include <cuda_fp16.h>
#include <cstdint>

// ============================================================================
// GraphConstructionActorHead — all N*N pair scores via factored 3-layer MLP.
//   pre: Ã[i]=fl16(emb_i@W1[:64]+b1), B̃[j]=fl16(emb_j@W1[64:]) (B̃ in a
//     transposed oct layout for coalesced chunk loads); per-node fp32
//     (sum,sumsq); W2^T fp16 swizzled; all small consts in one __constant__.
//   main: tile = 128 pairs (one i, 128 j). Warp owns 32 rows end-to-end.
//     Per chunk: B̃ block staged to smem once (ldmatrix-able, SW-swizzled).
//     Per tile: LN1 stats via tensor-core dot (A-op = B̃ frags, B-op = Ã
//     broadcast pairs; fp32 tables supply sums/sumsqs) -> x = HADD2(Ã,B̃) ->
//     LN1+ReLU in HFMA2 -> smem -> single-pass fp16 mma.sync GEMM (b2 in acc
//     init) -> LN2 stats fp32 (shfl) -> y half2 -> W3 dot via mma -> store.
//   4 CTAs/SM (best measured), jb = bid%8 so co-resident CTAs share the B̃
//   block, single wave.
// ============================================================================

#define NN 1024
#define GRID_MAIN 608              // 8 jblocks x 76 i-chunks; 4 CTAs/SM
#define IC_COUNT 76
#define SMEM_BYTES 41984

// ---------------- device scratch --------------------------------------------
__device__ __half g_Ah[NN * 64];            // fl16(A), row-major (128B/row)
__device__ __half g_Bth[NN * 64];           // fl16(B), [jb][oct][row][8 halves]
__device__ float2 g_stA[NN];                // fp32 (sum, sumsq) of A row
__device__ float2 g_stB[NN];
__device__ __half g_w2hi[64 * 64];          // [n][k] rows of 128B, XOR-swizzled
__device__ __align__(16) uint32_t g_alld[224];

// c_all layout (u32 idx): [0:32) g1h2 [32:64) be1h2 [64:96) w3h2
//                         [96:128) g2h2 [128:160) be2h2 [160:224) b2 float2
__constant__ __align__(16) uint32_t c_all[224];

// ---------------- PTX helpers (family-common only) --------------------------
__device__ __forceinline__ uint32_t smem_to_u32(const void* p) {
    uint32_t a;
    asm("{ .reg .u64 t; cvta.to.shared.u64 t, %1; cvt.u32.u64 %0, t; }"
        : "=r"(a) : "l"(p));
    return a;
}
__device__ __forceinline__ void ldm_x4(uint32_t* r, uint32_t addr) {
    asm volatile("ldmatrix.sync.aligned.m8n8.x4.shared.b16 {%0,%1,%2,%3}, [%4];"
                 : "=r"(r[0]), "=r"(r[1]), "=r"(r[2]), "=r"(r[3]) : "r"(addr));
}
__device__ __forceinline__ void mma_f16(float* c, const uint32_t* a,
                                        uint32_t b0, uint32_t b1) {
    asm volatile(
        "mma.sync.aligned.m16n8k16.row.col.f32.f16.f16.f32 "
        "{%0,%1,%2,%3}, {%4,%5,%6,%7}, {%8,%9}, {%0,%1,%2,%3};"
        : "+f"(c[0]), "+f"(c[1]), "+f"(c[2]), "+f"(c[3])
        : "r"(a[0]), "r"(a[1]), "r"(a[2]), "r"(a[3]), "r"(b0), "r"(b1));
}
__device__ __forceinline__ int swz(int row, int chunk) {
    return row * 128 + ((chunk ^ (row & 7)) << 4);
}
__device__ __forceinline__ uint32_t h2bits(__half2 h) { return *(uint32_t*)&h; }
__device__ __forceinline__ __half2 bits2h(uint32_t u) { return *(__half2*)&u; }

// ---------------- merged precompute (1 launch, 130 blocks x 512) ------------
__global__ void precompute_all(const float* __restrict__ emb,
                               const float* __restrict__ W1,
                               const float* __restrict__ b1,
                               const float* __restrict__ W2,
                               const float* __restrict__ g1, const float* __restrict__ be1,
                               const float* __restrict__ g2, const float* __restrict__ be2,
                               const float* __restrict__ W3, const float* __restrict__ b2) {
    int bid = blockIdx.x;
    int tid = threadIdx.x;
    if (bid < 128) {
        __shared__ float e[8][64];
        __shared__ float part[8][2][4];
        int g = tid >> 6, h = tid & 63;
        int n = bid * 8 + g;
        e[g][h] = emb[n * 64 + h];
        __syncthreads();
        float a0 = b1[h], a1 = 0.f, c0 = 0.f, c1 = 0.f;
#pragma unroll
        for (int d = 0; d < 64; d += 2) {
            float e0 = e[g][d], e1 = e[g][d + 1];
            a0 = fmaf(e0, __ldg(W1 + d * 64 + h), a0);
            a1 = fmaf(e1, __ldg(W1 + (d + 1) * 64 + h), a1);
            c0 = fmaf(e0, __ldg(W1 + (64 + d) * 64 + h), c0);
            c1 = fmaf(e1, __ldg(W1 + (65 + d) * 64 + h), c1);
        }
        float a = a0 + a1, b = c0 + c1;
        g_Ah[n * 64 + h] = __float2half_rn(a);
        // B̃ transposed-oct layout: [jb=n>>7][oct=h>>3][row=n&127][hh=h&7]
        g_Bth[((n >> 7) * 1024 + (h >> 3) * 128 + (n & 127)) * 8 + (h & 7)] =
            __float2half_rn(b);
        float sa = a, qa = a * a, sb = b, qb = b * b;
#pragma unroll
        for (int o = 16; o > 0; o >>= 1) {
            sa += __shfl_xor_sync(0xffffffffu, sa, o);
            qa += __shfl_xor_sync(0xffffffffu, qa, o);
            sb += __shfl_xor_sync(0xffffffffu, sb, o);
            qb += __shfl_xor_sync(0xffffffffu, qb, o);
        }
        int w = (tid >> 5) & 1;
        if ((tid & 31) == 0) {
            part[g][w][0] = sa; part[g][w][1] = qa;
            part[g][w][2] = sb; part[g][w][3] = qb;
        }
        __syncthreads();
        if (tid < 8) {
            int nn = bid * 8 + tid;
            g_stA[nn] = make_float2(part[tid][0][0] + part[tid][1][0],
                                    part[tid][0][1] + part[tid][1][1]);
            g_stB[nn] = make_float2(part[tid][0][2] + part[tid][1][2],
                                    part[tid][0][3] + part[tid][1][3]);
        }
    } else if (bid == 128) {
#pragma unroll
        for (int u = 0; u < 8; u++) {
            int idx = tid + 512 * u;               // 0..4095
            int k = idx >> 6, n = idx & 63;
            float v = W2[k * 64 + n];              // B[n][k] = W2[k][n]
            int byte = swz(n, k >> 3) + (k & 7) * 2;
            g_w2hi[byte >> 1] = __float2half_rn(v);
        }
    } else {
        if (tid < 32) {
            g_alld[tid]       = h2bits(__floats2half2_rn(g1[2 * tid], g1[2 * tid + 1]));
            g_alld[32 + tid]  = h2bits(__floats2half2_rn(be1[2 * tid], be1[2 * tid + 1]));
            g_alld[64 + tid]  = h2bits(__floats2half2_rn(W3[2 * tid], W3[2 * tid + 1]));
            g_alld[96 + tid]  = h2bits(__floats2half2_rn(g2[2 * tid], g2[2 * tid + 1]));
            g_alld[128 + tid] = h2bits(__floats2half2_rn(be2[2 * tid], be2[2 * tid + 1]));
            ((float2*)&g_alld[160])[tid] = make_float2(b2[2 * tid], b2[2 * tid + 1]);
        }
    }
}

// ---------------- main fused pair-MLP kernel --------------------------------
__global__ void __launch_bounds__(128, 4) pair_mlp_kernel(
    const float* __restrict__ mask, const float* __restrict__ b3p,
    float* __restrict__ out) {
    extern __shared__ char smem_raw[];
    uint32_t smem_u = smem_to_u32(smem_raw);
    uint32_t base = (smem_u + 1023) & ~1023u;
    char* basep = smem_raw + (base - smem_u);

    const uint32_t OFF_X  = 0;         // x fp16 [128 rows x 128B]   16 KB
    const uint32_t OFF_W2 = 16384;     // W2^T fp16 [64 x 128B]       8 KB
    const uint32_t OFF_BT = 24576;     // B̃ fp16 [128 rows x 128B]  16 KB

    int tid = threadIdx.x;
    int l = tid & 31;
    int wb = (tid >> 5) << 5;          // warp's 32-row slice base

    // copy pre-swizzled W2 into smem (startup only)
    {
        uint4* ph = (uint4*)(basep + OFF_W2);
        const uint4* shi = (const uint4*)g_w2hi;
#pragma unroll
        for (int t = 0; t < 4; t++) ph[tid + 128 * t] = __ldg(shi + tid + 128 * t);
    }
    __syncthreads();

    float b3 = __ldg(b3p);
    int arow_lo = ((l >> 3) & 1) * 8 + (l & 7);
    int asel = l >> 4;
    int brow = (l & 7);
    int bnb_hi = (l >> 4) & 1;
    int bchunk = (l >> 3) & 1;
    int c4 = l & 3;
    const float2* cb2 = (const float2*)&c_all[160];
    __half2 z2 = __float2half2_rn(0.f);

    // schedule: co-resident CTAs (bid ± k*152, 152 % 8 == 0) share jblock
    int jb = blockIdx.x & 7;
    int ic = blockIdx.x >> 3;          // 0..75
    int i0 = (ic * NN) / IC_COUNT;
    int i1 = ((ic + 1) * NN) / IC_COUNT;
    int jbase = jb << 7;

    // stage B̃ block into smem once per chunk (warp-private rows)
    {
        const uint4* src = (const uint4*)g_Bth + (size_t)jb * 1024 + wb + l;
#pragma unroll
        for (int o = 0; o < 8; o++) {
            uint4 v = __ldg(src + o * 128);
            *(uint4*)(basep + OFF_BT + swz(wb + l, o)) = v;
        }
    }
    __syncwarp();

    // per-chunk invariant hoists
    float2 stB = __ldg(g_stB + jbase + tid);
    int jj = jbase + wb + l;
    const float* maskp = mask + jj;
    float* outp = out + jj;
    int src4 = (l & 7) * 4;            // gather source lane

    for (int i = i0; i < i1; i++) {
        // ---- Ã broadcast row (8 uint4 = 64 halves) -------------------------
        uint4 ah[8];
        {
            const uint4* Ap = (const uint4*)g_Ah + i * 8;
#pragma unroll
            for (int t = 0; t < 8; t++) ah[t] = __ldg(Ap + t);
        }

        // ---- LN1 stats: dot via tensor core --------------------------------
        // D[r, n] = Σ_k B̃[r,k]·Ã[k]  (B-operand replicated across n)
        float dc0[4] = {0.f, 0.f, 0.f, 0.f};
        float dc1[4] = {0.f, 0.f, 0.f, 0.f};
#pragma unroll
        for (int kc = 0; kc < 4; kc++) {
            const char* abase = (const char*)g_Ah + i * 128 + 32 * kc + 4 * c4;
            uint32_t b0 = *(const uint32_t*)abase;          // Ã[16kc+2c4, +1]
            uint32_t b1 = *(const uint32_t*)(abase + 16);   // Ã[16kc+8+2c4, +1]
            uint32_t bf[4];
            ldm_x4(bf, base + OFF_BT + swz(wb + arow_lo, kc * 2 + asel));
            mma_f16(dc0, bf, b0, b1);
            ldm_x4(bf, base + OFF_BT + swz(wb + 16 + arow_lo, kc * 2 + asel));
            mma_f16(dc1, bf, b0, b1);
        }
        // gather: row wb+l's dot (same pattern as final-score gather)
        float e0 = __shfl_sync(0xffffffffu, dc0[0], src4);
        float e1 = __shfl_sync(0xffffffffu, dc0[2], src4);
        float e2 = __shfl_sync(0xffffffffu, dc1[0], src4);
        float e3 = __shfl_sync(0xffffffffu, dc1[2], src4);
        float dot = (l < 8) ? e0 : (l < 16) ? e1 : (l < 24) ? e2 : e3;

        float2 stA = __ldg(g_stA + i);
        float m  = (stA.x + stB.x) * (1.f / 64.f);
        float v  = (stA.y + stB.y + 2.f * dot) * (1.f / 64.f) - m * m;
        float rs = rsqrtf(v + 1e-5f);
        float nm = -m * rs;

        // ---- x = Ã + B̃ (half2), LN1 + ReLU, STS to x-tile -----------------
        __half2 rsh = __float2half2_rn(rs);
        __half2 nmh = __float2half2_rn(nm);
#pragma unroll
        for (int c = 0; c < 8; c++) {
            uint4 bv = *(uint4*)(basep + OFF_BT + swz(tid, c));   // own row
            uint32_t hiw[4];
            uint32_t av[4] = {ah[c].x, ah[c].y, ah[c].z, ah[c].w};
            uint32_t bw[4] = {bv.x, bv.y, bv.z, bv.w};
#pragma unroll
            for (int u = 0; u < 4; u++) {
                int k2 = 4 * c + u;
                __half2 x = __hadd2(bits2h(av[u]), bits2h(bw[u]));
                __half2 u0 = __hfma2(x, rsh, nmh);
                __half2 h = __hmax2(__hfma2(u0, bits2h(c_all[k2]),
                                            bits2h(c_all[32 + k2])), z2);
                hiw[u] = h2bits(h);
            }
            *(uint4*)(basep + OFF_X + swz(tid, c)) =
                make_uint4(hiw[0], hiw[1], hiw[2], hiw[3]);
        }
        __syncwarp();   // warp-private rows: only intra-warp visibility needed

        // ---- layer 2 GEMM: single-pass fp16, b2 in accumulator init --------
        float acc[2][8][4];
#pragma unroll
        for (int nb = 0; nb < 8; nb++) {
            float2 bb = cb2[nb * 4 + c4];          // (b2[col], b2[col+1])
            acc[0][nb][0] = bb.x; acc[0][nb][1] = bb.y;
            acc[0][nb][2] = bb.x; acc[0][nb][3] = bb.y;
            acc[1][nb][0] = bb.x; acc[1][nb][1] = bb.y;
            acc[1][nb][2] = bb.x; acc[1][nb][3] = bb.y;
        }
#pragma unroll
        for (int kc = 0; kc < 4; kc++) {
            uint32_t ahi0[4], ahi1[4];
            ldm_x4(ahi0, base + OFF_X + swz(wb + arow_lo, kc * 2 + asel));
            ldm_x4(ahi1, base + OFF_X + swz(wb + 16 + arow_lo, kc * 2 + asel));
#pragma unroll
            for (int p = 0; p < 4; p++) {
                uint32_t r[4];
                ldm_x4(r, base + OFF_W2 +
                           swz((2 * p + bnb_hi) * 8 + brow, kc * 2 + bchunk));
                mma_f16(acc[0][2 * p],     ahi0, r[0], r[1]);
                mma_f16(acc[1][2 * p],     ahi1, r[0], r[1]);
                mma_f16(acc[0][2 * p + 1], ahi0, r[2], r[3]);
                mma_f16(acc[1][2 * p + 1], ahi1, r[2], r[3]);
            }
        }

        // ---- LN2 stats fp32 (b2 already in acc), shfl reduce ---------------
        float rs0[2], nm0[2], rs1[2], nm1[2];
#pragma unroll
        for (int mf = 0; mf < 2; mf++) {
            float su0 = 0, qu0 = 0, su1 = 0, qu1 = 0;
#pragma unroll
            for (int nb = 0; nb < 8; nb++) {
                float a0 = acc[mf][nb][0], a1 = acc[mf][nb][1];
                float a2 = acc[mf][nb][2], a3 = acc[mf][nb][3];
                su0 += a0 + a1; qu0 = fmaf(a0, a0, fmaf(a1, a1, qu0));
                su1 += a2 + a3; qu1 = fmaf(a2, a2, fmaf(a3, a3, qu1));
            }
            su0 += __shfl_xor_sync(0xffffffffu, su0, 1);
            su0 += __shfl_xor_sync(0xffffffffu, su0, 2);
            qu0 += __shfl_xor_sync(0xffffffffu, qu0, 1);
            qu0 += __shfl_xor_sync(0xffffffffu, qu0, 2);
            su1 += __shfl_xor_sync(0xffffffffu, su1, 1);
            su1 += __shfl_xor_sync(0xffffffffu, su1, 2);
            qu1 += __shfl_xor_sync(0xffffffffu, qu1, 1);
            qu1 += __shfl_xor_sync(0xffffffffu, qu1, 2);
            float m0 = su0 * (1.f / 64.f);
            float v0 = qu0 * (1.f / 64.f) - m0 * m0;
            rs0[mf] = rsqrtf(v0 + 1e-5f); nm0[mf] = -m0 * rs0[mf];
            float m1 = su1 * (1.f / 64.f);
            float v1 = qu1 * (1.f / 64.f) - m1 * m1;
            rs1[mf] = rsqrtf(v1 + 1e-5f); nm1[mf] = -m1 * rs1[mf];
        }

        // ---- y = relu(LN2) in half2 -> W3 dot via mma (b3 in acc init) -----
        float w00, w01, w10, w11;
#pragma unroll
        for (int mf = 0; mf < 2; mf++) {
            float c2[4] = {b3, b3, b3, b3};
            __half2 rg = __float2half2_rn(rs0[mf]), ng = __float2half2_rn(nm0[mf]);
            __half2 r8 = __float2half2_rn(rs1[mf]), n8 = __float2half2_rn(nm1[mf]);
#pragma unroll
            for (int p = 0; p < 4; p++) {
                int nA = 2 * p, nB = 2 * p + 1;
                int kA = nA * 4 + c4, kB = nB * 4 + c4;   // half2 col-pair idx
                __half2 gA = bits2h(c_all[96 + kA]), bA = bits2h(c_all[128 + kA]);
                __half2 gB = bits2h(c_all[96 + kB]), bB = bits2h(c_all[128 + kB]);
                uint32_t af[4];
                __half2 zz, uu;
                zz = __floats2half2_rn(acc[mf][nA][0], acc[mf][nA][1]);
                uu = __hfma2(zz, rg, ng);
                af[0] = h2bits(__hmax2(__hfma2(uu, gA, bA), z2));
                zz = __floats2half2_rn(acc[mf][nA][2], acc[mf][nA][3]);
                uu = __hfma2(zz, r8, n8);
                af[1] = h2bits(__hmax2(__hfma2(uu, gA, bA), z2));
                zz = __floats2half2_rn(acc[mf][nB][0], acc[mf][nB][1]);
                uu = __hfma2(zz, rg, ng);
                af[2] = h2bits(__hmax2(__hfma2(uu, gB, bB), z2));
                zz = __floats2half2_rn(acc[mf][nB][2], acc[mf][nB][3]);
                uu = __hfma2(zz, r8, n8);
                af[3] = h2bits(__hmax2(__hfma2(uu, gB, bB), z2));
                mma_f16(c2, af, c_all[64 + 8 * p + c4], c_all[64 + 8 * p + c4 + 4]);
            }
            if (mf == 0) { w00 = c2[0]; w01 = c2[2]; }
            else         { w10 = c2[0]; w11 = c2[2]; }
        }

        // gather so lane l holds row wb+l -> coalesced mask load + store
        float a0 = __shfl_sync(0xffffffffu, w00, src4);
        float a1 = __shfl_sync(0xffffffffu, w01, src4);
        float a2 = __shfl_sync(0xffffffffu, w10, src4);
        float a3 = __shfl_sync(0xffffffffu, w11, src4);
        float dv = (l < 8) ? a0 : (l < 16) ? a1 : (l < 24) ? a2 : a3;
        float sc = dv * __ldg(maskp + (i << 10));
        outp[i << 10] = (jj == i) ? 0.f : sc;

        __syncwarp();   // lanes rejoin before next tile's STS to the warp slice
    }
}

// ---------------- launch ----------------------------------------------------
extern "C" void kernel_launch(void* const* d_in, const int* in_sizes, int n_in,
                              void* d_out, int out_size) {
    const float* emb  = (const float*)d_in[0];
    const float* mask = (const float*)d_in[1];
    const float* W1   = (const float*)d_in[2];
    const float* b1   = (const float*)d_in[3];
    const float* g1   = (const float*)d_in[4];
    const float* be1  = (const float*)d_in[5];
    const float* W2   = (const float*)d_in[6];
    const float* b2   = (const float*)d_in[7];
    const float* g2   = (const float*)d_in[8];
    const float* be2  = (const float*)d_in[9];
    const float* W3   = (const float*)d_in[10];
    const float* b3   = (const float*)d_in[11];
    float* out = (float*)d_out;

    cudaFuncSetAttribute(pair_mlp_kernel,
                         cudaFuncAttributeMaxDynamicSharedMemorySize, SMEM_BYTES);

    precompute_all<<<130, 512>>>(emb, W1, b1, W2, g1, be1, g2, be2, W3, b2);

    // stage packed consts into __constant__ (single async D2D copy)
    void* pall = nullptr;
    cudaGetSymbolAddress(&pall, g_alld);
    cudaMemcpyToSymbolAsync(c_all, pall, 224 * sizeof(uint32_t), 0,
                            cudaMemcpyDeviceToDevice, 0);

    pair_mlp_kernel<<<GRID_MAIN, 128, SMEM_BYTES>>>(mask, b3, out);
}